// round 16
// baseline (speedup 1.0000x reference)
#include <cuda_runtime.h>
#include <cuda_fp16.h>
#include <cstdint>

#define DEVINL __device__ __forceinline__

// ----------------------------------------------------------------------------
// w_bin pre-packed as mma.sync m16n8k16 B-fragments (fp16, "col" operand),
// two nb per uint4 for LDS.128:
//   word idx = ((kc*8 + nb/2)*32 + lane)*4 + (nb&1)*2 + j
//   (lane = (f&7)*4 + (kk>>1), j = k-half, half = kk&1 — proven R9/R13/R15)
// 32 KB total.
// ----------------------------------------------------------------------------
__device__ __align__(16) unsigned char g_bfrag[32768];

// ----------------------------------------------------------------------------
// Threefry2x32-20 (JAX permutation) — PARTITIONABLE output scheme (proven R8)
// ----------------------------------------------------------------------------
DEVINL uint32_t rotl32(uint32_t x, int r) { return (x << r) | (x >> (32 - r)); }

DEVINL void threefry2x32(uint32_t k0, uint32_t k1, uint32_t& x0, uint32_t& x1) {
    uint32_t ks0 = k0, ks1 = k1, ks2 = k0 ^ k1 ^ 0x1BD11BDAu;
    x0 += ks0; x1 += ks1;
#define TF_ROUND(r) { x0 += x1; x1 = rotl32(x1, r) ^ x0; }
    TF_ROUND(13) TF_ROUND(15) TF_ROUND(26) TF_ROUND(6)
    x0 += ks1; x1 += ks2 + 1u;
    TF_ROUND(17) TF_ROUND(29) TF_ROUND(16) TF_ROUND(24)
    x0 += ks2; x1 += ks0 + 2u;
    TF_ROUND(13) TF_ROUND(15) TF_ROUND(26) TF_ROUND(6)
    x0 += ks0; x1 += ks1 + 3u;
    TF_ROUND(17) TF_ROUND(29) TF_ROUND(16) TF_ROUND(24)
    x0 += ks1; x1 += ks2 + 4u;
    TF_ROUND(13) TF_ROUND(15) TF_ROUND(26) TF_ROUND(6)
    x0 += ks2; x1 += ks0 + 5u;
#undef TF_ROUND
}

// Store w_bin[d][f] (d = K index, f = N index) into B-fragment layout (fp16).
DEVINL void wbin_store(int lin_idx, float s) {
    int d = lin_idx >> 7;      // weight row  -> k
    int f = lin_idx & 127;     // weight col  -> n
    int kc = d >> 4, dk = d & 15;
    int nb = f >> 3;
    int j    = dk >> 3;
    int kk   = dk & 7;
    int lane = (f & 7) * 4 + (kk >> 1);
    int half = kk & 1;
    uint32_t widx = (uint32_t)((((kc * 8 + (nb >> 1)) * 32 + lane) * 4) +
                               ((nb & 1) * 2 + j));
    *(__half*)(g_bfrag + widx * 4 + half * 2) = __float2half_rn(s);
}

// Partitionable threefry: element i -> counter (0, i), bits = out0 ^ out1.
__global__ void wbin_kernel(const float* __restrict__ weight,
                            const int* __restrict__ seed_p,
                            const int* __restrict__ train_p) {
    int i = blockIdx.x * blockDim.x + threadIdx.x;
    if (i >= 16384) return;
    float s;
    if (*train_p) {
        uint32_t x0 = 0u, x1 = (uint32_t)i;
        threefry2x32(0u, (uint32_t)(*seed_p), x0, x1);
        uint32_t bits = x0 ^ x1;
        float u = __uint_as_float(0x3f800000u | (bits >> 9)) - 1.0f;
        float w = weight[i];
        float p = fminf(fmaxf(__fmul_rn(__fadd_rn(w, 1.0f), 0.5f), 0.0f), 1.0f);
        s = (u < p) ? 1.0f : -1.0f;
    } else {
        s = (weight[i] > 0.0f) ? 1.0f : -1.0f;
    }
    wbin_store(i, s);
}

// ----------------------------------------------------------------------------
// mma helper (fp16, fp32 accumulate)
// ----------------------------------------------------------------------------
DEVINL void mma_f16(float& c0, float& c1, float& c2, float& c3,
                    uint32_t a0, uint32_t a1, uint32_t a2, uint32_t a3,
                    uint32_t b0, uint32_t b1) {
    asm volatile(
        "mma.sync.aligned.m16n8k16.row.col.f32.f16.f16.f32 "
        "{%0,%1,%2,%3}, {%4,%5,%6,%7}, {%8,%9}, {%0,%1,%2,%3};"
        : "+f"(c0), "+f"(c1), "+f"(c2), "+f"(c3)
        : "r"(a0), "r"(a1), "r"(a2), "r"(a3), "r"(b0), "r"(b1));
}

DEVINL uint32_t f16x2(float x, float y) {
    uint32_t h;
    asm("cvt.rn.f16x2.f32 %0, %1, %2;" : "=r"(h) : "f"(y), "f"(x));
    return h;
}

// ----------------------------------------------------------------------------
// GEMM kernel: one 256x128 output tile per CTA, 256 threads (8 warps).
// Warp w computes an m32n128 slab: rows [32w, 32w+32) x all 128 cols —
// two m16 fragment groups sharing every B LDS.128 (4 MMAs per B load,
// halving B SMEM-read amplification vs m16 warps).
// A loaded DIRECTLY from GMEM in fragment layout (R11-proven cheapest path).
// 1 CTA/SM (128 accum regs); deep ILP via full unroll + 1-chunk prefetch.
// ----------------------------------------------------------------------------
__global__ void __launch_bounds__(256, 1)
gemm_kernel(const float* __restrict__ inp, float* __restrict__ out) {
    __shared__ __align__(16) unsigned char smemB[32768];
    const int tid  = threadIdx.x;
    const int w    = tid >> 5;
    const int lane = tid & 31;

    // --- B fragments: straight 32 KB copy (L2-resident, shared by all CTAs) ---
    {
        const uint4* src = (const uint4*)g_bfrag;
        uint4* dst = (uint4*)smemB;
#pragma unroll
        for (int i = 0; i < 8; i++) dst[tid + i * 256] = src[tid + i * 256];
    }
    __syncthreads();

    const int r0 = 32 * w + (lane >> 2);
    const float* base = inp + (size_t)blockIdx.x * (256 * 128) +
                        (size_t)r0 * 128 + (lane & 3) * 2;
    const float* aP[4] = { base, base + 8 * 128, base + 16 * 128, base + 24 * 128 };
    const uint4* bfr = (const uint4*)smemB;

    float c0[16][4], c1[16][4];
#pragma unroll
    for (int nb = 0; nb < 16; nb++)
#pragma unroll
        for (int q = 0; q < 4; q++) { c0[nb][q] = 0.0f; c1[nb][q] = 0.0f; }

    // Prefetched A pairs: g-th row group (r0 + 8g), k-halves 0 / 8.
    float2 x[4][2];
#pragma unroll
    for (int g = 0; g < 4; g++) {
        x[g][0] = __ldcs((const float2*)(aP[g]));
        x[g][1] = __ldcs((const float2*)(aP[g] + 8));
    }

#pragma unroll
    for (int kc = 0; kc < 8; kc++) {
        float2 n[4][2];
        if (kc < 7) {
#pragma unroll
            for (int g = 0; g < 4; g++) {
                const float* p = aP[g] + (kc + 1) * 16;
                n[g][0] = __ldcs((const float2*)(p));
                n[g][1] = __ldcs((const float2*)(p + 8));
            }
        }

        // Fragment order per m16 group: a0=(r,k0) a1=(r+8,k0) a2=(r,k8) a3=(r+8,k8)
        uint32_t p0 = f16x2(x[0][0].x, x[0][0].y);   // group0 rows r0
        uint32_t p1 = f16x2(x[1][0].x, x[1][0].y);   // group0 rows r0+8
        uint32_t p2 = f16x2(x[0][1].x, x[0][1].y);
        uint32_t p3 = f16x2(x[1][1].x, x[1][1].y);
        uint32_t q0 = f16x2(x[2][0].x, x[2][0].y);   // group1 rows r0+16
        uint32_t q1 = f16x2(x[3][0].x, x[3][0].y);   // group1 rows r0+24
        uint32_t q2 = f16x2(x[2][1].x, x[2][1].y);
        uint32_t q3 = f16x2(x[3][1].x, x[3][1].y);

        const uint4* bk = bfr + kc * 8 * 32 + lane;
#pragma unroll
        for (int nbp = 0; nbp < 8; nbp++) {
            uint4 b = bk[nbp * 32];
            mma_f16(c0[2 * nbp][0], c0[2 * nbp][1], c0[2 * nbp][2], c0[2 * nbp][3],
                    p0, p1, p2, p3, b.x, b.y);
            mma_f16(c0[2 * nbp + 1][0], c0[2 * nbp + 1][1],
                    c0[2 * nbp + 1][2], c0[2 * nbp + 1][3],
                    p0, p1, p2, p3, b.z, b.w);
            mma_f16(c1[2 * nbp][0], c1[2 * nbp][1], c1[2 * nbp][2], c1[2 * nbp][3],
                    q0, q1, q2, q3, b.x, b.y);
            mma_f16(c1[2 * nbp + 1][0], c1[2 * nbp + 1][1],
                    c1[2 * nbp + 1][2], c1[2 * nbp + 1][3],
                    q0, q1, q2, q3, b.z, b.w);
        }

#pragma unroll
        for (int g = 0; g < 4; g++) { x[g][0] = n[g][0]; x[g][1] = n[g][1]; }
    }

    // --- Epilogue: direct streaming STG.64 (full 32B sectors per 4 lanes) ---
    {
        const int orow = (int)(blockIdx.x * 256) + 32 * w + (lane >> 2);
        const int cb = 2 * (lane & 3);
        float* o0 = out + (size_t)orow * 128 + cb;          // rows r0
        float* o1 = o0 + (size_t)8 * 128;                   // rows r0+8
        float* o2 = o0 + (size_t)16 * 128;                  // rows r0+16
        float* o3 = o0 + (size_t)24 * 128;                  // rows r0+24
#pragma unroll
        for (int nb = 0; nb < 16; nb++) {
            __stcs((float2*)(o0 + nb * 8), make_float2(c0[nb][0], c0[nb][1]));
            __stcs((float2*)(o1 + nb * 8), make_float2(c0[nb][2], c0[nb][3]));
            __stcs((float2*)(o2 + nb * 8), make_float2(c1[nb][0], c1[nb][1]));
            __stcs((float2*)(o3 + nb * 8), make_float2(c1[nb][2], c1[nb][3]));
        }
    }
}

// ----------------------------------------------------------------------------
extern "C" void kernel_launch(void* const* d_in, const int* in_sizes, int n_in,
                              void* d_out, int out_size) {
    // Resolve pointers by size (robust to metadata ordering).
    int ii = 0, wi = 1, si = 2, ti = 3;
    {
        int small[4]; int ns = 0;
        for (int i = 0; i < n_in; i++) {
            if (in_sizes[i] == 16384) wi = i;
            else if (in_sizes[i] > 100000) ii = i;
            else if (ns < 4) small[ns++] = i;
        }
        if (ns >= 2) { si = small[0]; ti = small[1]; }
        else if (ns == 1) { si = small[0]; ti = small[0]; }
    }
    const float* inputs = (const float*)d_in[ii];
    const float* weight = (const float*)d_in[wi];
    const int*   seed   = (const int*)d_in[si];
    const int*   train  = (const int*)d_in[ti];
    float* out = (float*)d_out;

    int n_rows  = in_sizes[ii] / 128;   // 1048576
    int n_tiles = n_rows / 256;         // 4096

    wbin_kernel<<<64, 256>>>(weight, seed, train);
    gemm_kernel<<<n_tiles, 256>>>(inputs, out);
}